// round 2
// baseline (speedup 1.0000x reference)
#include <cuda_runtime.h>
#include <cuda_bf16.h>
#include <math.h>

// Problem constants
#define Bq    4
#define CH_G  64
#define Hh    240
#define Ww    320
#define HW    (Hh*Ww)          // 76800
#define NUM   8
#define C_FEA 8
#define COUT  24
#define Pn    (HW*NUM)         // 614400
#define HIN   120
#define WIN   160

// Scratch (device globals; no runtime allocation allowed)
__device__ __align__(16) float g_oa[(size_t)Bq*COUT*HW];       // conv output  (29.5 MB)
__device__ __align__(16) float g_feaT[(size_t)Bq*HW*C_FEA];    // upsampled fea, channel-last (9.8 MB)
__device__ __align__(16) float g_smp[(size_t)Bq*C_FEA*Pn];     // sampled tensor (78.6 MB)

// ---------------------------------------------------------------------------
// Stage 1: 2x bilinear upsample (jax.image.resize "bilinear" semantics:
// half-pixel centers -> weights {0.75,0.25}, edge renorm == index clamp).
// Output stored channel-last: g_feaT[b][i][j][c].
// ---------------------------------------------------------------------------
__global__ void upsample_kernel(const float* __restrict__ fea) {
    int t = blockIdx.x * 256 + threadIdx.x;
    if (t >= Bq * HW) return;
    int b = t / HW; int pix = t - b * HW;
    int i = pix / Ww; int j = pix - i * Ww;

    int ky = i >> 1;
    int y1 = (i & 1) ? min(ky + 1, HIN - 1) : max(ky - 1, 0);
    int kx = j >> 1;
    int x1 = (j & 1) ? min(kx + 1, WIN - 1) : max(kx - 1, 0);
    const float wm = 0.75f, ws = 0.25f;

    float* dst = &g_feaT[(size_t)t * C_FEA];
#pragma unroll
    for (int c = 0; c < C_FEA; c++) {
        const float* fp = fea + ((size_t)(b * C_FEA + c)) * (HIN * WIN);
        float v00 = fp[ky * WIN + kx];
        float v01 = fp[ky * WIN + x1];
        float v10 = fp[y1 * WIN + kx];
        float v11 = fp[y1 * WIN + x1];
        dst[c] = wm * (wm * v00 + ws * v01) + ws * (wm * v10 + ws * v11);
    }
}

// ---------------------------------------------------------------------------
// Stage 2: 3x3 conv, 64 -> 24 channels, pad 1, + bias.  Tile 8x32 pixels,
// 16-channel smem chunks. Weights in smem as [c][k][24] so the 24-output
// inner loop uses float4 broadcast LDS (keeps the kernel FMA-pipe bound).
// ---------------------------------------------------------------------------
__global__ __launch_bounds__(256) void conv_kernel(const float* __restrict__ gin,
                                                   const float* __restrict__ wgt,
                                                   const float* __restrict__ bias) {
    __shared__ __align__(16) float sg[16 * 10 * 34];   // 16ch x (8+2) x (32+2)
    __shared__ __align__(16) float sw[16 * 9 * 24];    // [c][k][o]

    int tx = threadIdx.x & 31, ty = threadIdx.x >> 5;
    int bx = blockIdx.x * 32, by = blockIdx.y * 8, b = blockIdx.z;

    float acc[COUT];
#pragma unroll
    for (int o = 0; o < COUT; o++) acc[o] = bias[o];

    for (int cc = 0; cc < 4; cc++) {
        __syncthreads();
        // load guidance tile (with zero pad halo)
        for (int idx = threadIdx.x; idx < 16 * 340; idx += 256) {
            int c = idx / 340; int r = idx - c * 340;
            int yy = r / 34;   int xx = r - yy * 34;
            int gy = by + yy - 1, gx = bx + xx - 1;
            float v = 0.f;
            if (gy >= 0 && gy < Hh && gx >= 0 && gx < Ww)
                v = gin[((size_t)(b * CH_G + cc * 16 + c)) * HW + gy * Ww + gx];
            sg[idx] = v;
        }
        // load weight chunk, layout [c][k][o]
        for (int idx = threadIdx.x; idx < 16 * 216; idx += 256) {
            int c = idx / 216; int r = idx - c * 216;
            int k = r / 24;    int o = r - k * 24;
            sw[idx] = wgt[((size_t)o * CH_G + cc * 16 + c) * 9 + k];
        }
        __syncthreads();

        for (int c = 0; c < 16; c++) {
            float g[9];
#pragma unroll
            for (int dy = 0; dy < 3; dy++)
#pragma unroll
                for (int dx = 0; dx < 3; dx++)
                    g[dy * 3 + dx] = sg[c * 340 + (ty + dy) * 34 + (tx + dx)];
#pragma unroll
            for (int k = 0; k < 9; k++) {
                const float4* wv = (const float4*)&sw[(c * 9 + k) * 24];
                float gk = g[k];
#pragma unroll
                for (int q = 0; q < 6; q++) {
                    float4 w4 = wv[q];
                    acc[q * 4 + 0] += w4.x * gk;
                    acc[q * 4 + 1] += w4.y * gk;
                    acc[q * 4 + 2] += w4.z * gk;
                    acc[q * 4 + 3] += w4.w * gk;
                }
            }
        }
    }

    int gy = by + ty, gx = bx + tx;
    size_t pix = (size_t)gy * Ww + gx;
#pragma unroll
    for (int o = 0; o < COUT; o++)
        g_oa[((size_t)(b * COUT + o)) * HW + pix] = acc[o];
}

// ---------------------------------------------------------------------------
// Stage 3: deformable sampling of fea_up (8 channels per sample point).
// Faithful coordinate construction: for offset index n, x = oa[2n] + base,
// y = oa[2n+1] + base, where base = i (row) for n<4 and j (col) for n>=4.
// Bilinear with zero padding. Writes g_smp[b][c][p], p = pix*8 + n.
// ---------------------------------------------------------------------------
__global__ void sample_kernel() {
    int t = blockIdx.x * 256 + threadIdx.x;
    if (t >= Bq * Pn) return;
    int b = t / Pn; int p = t - b * Pn;
    int pix = p >> 3; int n = p & 7;
    int i = pix / Ww; int j = pix - i * Ww;

    float offx = g_oa[((size_t)(b * COUT + 2 * n)) * HW + pix];
    float offy = g_oa[((size_t)(b * COUT + 2 * n + 1)) * HW + pix];
    float base = (n < 4) ? (float)i : (float)j;
    float x = offx + base;
    float y = offy + base;

    float x0 = floorf(x), y0 = floorf(y);
    float fx = x - x0, fy = y - y0;

    float acc0 = 0, acc1 = 0, acc2 = 0, acc3 = 0, acc4 = 0, acc5 = 0, acc6 = 0, acc7 = 0;
    const float* fb = g_feaT + (size_t)b * HW * C_FEA;
#pragma unroll
    for (int cy = 0; cy < 2; cy++) {
#pragma unroll
        for (int cx = 0; cx < 2; cx++) {
            float xi = x0 + cx, yi = y0 + cy;
            float wgt = (cy ? fy : 1.f - fy) * (cx ? fx : 1.f - fx);
            if (xi >= 0.f && xi <= (float)(Ww - 1) && yi >= 0.f && yi <= (float)(Hh - 1)) {
                int xc = (int)xi, yc = (int)yi;
                const float4* v = (const float4*)(fb + ((size_t)yc * Ww + xc) * C_FEA);
                float4 v0 = v[0], v1 = v[1];
                acc0 += wgt * v0.x; acc1 += wgt * v0.y; acc2 += wgt * v0.z; acc3 += wgt * v0.w;
                acc4 += wgt * v1.x; acc5 += wgt * v1.y; acc6 += wgt * v1.z; acc7 += wgt * v1.w;
            }
        }
    }
    float* sb = g_smp + (size_t)b * C_FEA * Pn;
    sb[(size_t)0 * Pn + p] = acc0;
    sb[(size_t)1 * Pn + p] = acc1;
    sb[(size_t)2 * Pn + p] = acc2;
    sb[(size_t)3 * Pn + p] = acc3;
    sb[(size_t)4 * Pn + p] = acc4;
    sb[(size_t)5 * Pn + p] = acc5;
    sb[(size_t)6 * Pn + p] = acc6;
    sb[(size_t)7 * Pn + p] = acc7;
}

// single-channel bilinear with zero padding (reference _bilinear_zeros)
__device__ __forceinline__ float bil1(const float* __restrict__ img, float x, float y) {
    float x0 = floorf(x), y0 = floorf(y);
    float fx = x - x0, fy = y - y0;
    float r = 0.f;
#pragma unroll
    for (int cy = 0; cy < 2; cy++) {
#pragma unroll
        for (int cx = 0; cx < 2; cx++) {
            float xi = x0 + cx, yi = y0 + cy;
            if (xi >= 0.f && xi <= (float)(Ww - 1) && yi >= 0.f && yi <= (float)(Hh - 1)) {
                float wgt = (cy ? fy : 1.f - fy) * (cx ? fx : 1.f - fx);
                r += wgt * img[(int)yi * Ww + (int)xi];
            }
        }
    }
    return r;
}

// ---------------------------------------------------------------------------
// Stage 4: fused epilogue.  Replicates the reference's raw-reshape scramble:
// cos_w[c](pix) = sum_a fea[a] * g_smp[b][Q/76800][(Q%76800)*8 + c], Q=pix*8+a.
// Then TGASS tanh scaling, confidence bilinear on gt_depth_conf, abs-sum
// normalize + clamp, reference channel insert, softmax, write both outputs.
// ---------------------------------------------------------------------------
__global__ void final_kernel(const float* __restrict__ gt,
                             const float* __restrict__ ascp,
                             float* __restrict__ out) {
    int t = blockIdx.x * 256 + threadIdx.x;
    if (t >= Bq * HW) return;
    int b = t / HW; int pix = t - b * HW;
    int i = pix / Ww; int j = pix - i * Ww;

    float o[COUT];
#pragma unroll
    for (int k = 0; k < COUT; k++) o[k] = g_oa[((size_t)(b * COUT + k)) * HW + pix];

    const float4* fv = (const float4*)&g_feaT[(size_t)t * C_FEA];
    float4 f0 = fv[0], f1 = fv[1];
    float fea[8] = {f0.x, f0.y, f0.z, f0.w, f1.x, f1.y, f1.z, f1.w};

    float cw0 = 0, cw1 = 0, cw2 = 0, cw3 = 0, cw4 = 0, cw5 = 0, cw6 = 0, cw7 = 0;
#pragma unroll
    for (int a = 0; a < 8; a++) {
        int Q  = pix * 8 + a;
        int ch = Q / HW;
        int p2 = Q - ch * HW;
        const float4* sp = (const float4*)&g_smp[((size_t)(b * C_FEA + ch)) * Pn + (size_t)p2 * 8];
        float4 s0 = sp[0], s1 = sp[1];
        float fa = fea[a];
        cw0 += fa * s0.x; cw1 += fa * s0.y; cw2 += fa * s0.z; cw3 += fa * s0.w;
        cw4 += fa * s1.x; cw5 += fa * s1.y; cw6 += fa * s1.z; cw7 += fa * s1.w;
    }
    float cosw[8] = {cw0, cw1, cw2, cw3, cw4, cw5, cw6, cw7};

    float denom = ascp[0] + 1e-8f;
    const float* gb = gt + (size_t)b * HW;

    float aff[8];
#pragma unroll
    for (int n = 0; n < 8; n++) {
        float a0 = tanhf(o[16 + n] * cosw[n]) / denom;
        float y = o[2 * n]     + (float)i;   // channel 0 = dy
        float x = o[2 * n + 1] + (float)j;   // channel 1 = dx
        aff[n] = a0 * bil1(gb, x, y);
    }

    float sabs = 0.f;
#pragma unroll
    for (int n = 0; n < 8; n++) sabs += fabsf(aff[n]);
    sabs += 1e-4f;
    sabs = fmaxf(sabs, 1.0f);

    float ssum = 0.f;
#pragma unroll
    for (int n = 0; n < 8; n++) { aff[n] = aff[n] / sabs; ssum += aff[n]; }

    float v[9];
    v[0] = aff[0]; v[1] = aff[1]; v[2] = aff[2]; v[3] = aff[3];
    v[4] = 1.0f - ssum;
    v[5] = aff[4]; v[6] = aff[5]; v[7] = aff[6]; v[8] = aff[7];

    float m = v[0];
#pragma unroll
    for (int k = 1; k < 9; k++) m = fmaxf(m, v[k]);
    float e[9], es = 0.f;
#pragma unroll
    for (int k = 0; k < 9; k++) { e[k] = expf(v[k] - m); es += e[k]; }
    float inv = 1.0f / es;

    // output: offset_full (B,18,H,W) flattened, then aff_full (B,9,H,W)
    const size_t OFFA = (size_t)Bq * 18 * HW;
#pragma unroll
    for (int k = 0; k < 8; k++)
        out[((size_t)(b * 18 + k)) * HW + pix] = o[k];
    out[((size_t)(b * 18 + 8)) * HW + pix] = 0.f;
    out[((size_t)(b * 18 + 9)) * HW + pix] = 0.f;
#pragma unroll
    for (int k = 10; k < 18; k++)
        out[((size_t)(b * 18 + k)) * HW + pix] = o[k - 2];
#pragma unroll
    for (int k = 0; k < 9; k++)
        out[OFFA + ((size_t)(b * 9 + k)) * HW + pix] = e[k] * inv;
}

// ---------------------------------------------------------------------------
extern "C" void kernel_launch(void* const* d_in, const int* in_sizes, int n_in,
                              void* d_out, int out_size) {
    const float* guidance = (const float*)d_in[0];
    const float* gt       = (const float*)d_in[1];
    const float* fea      = (const float*)d_in[2];
    const float* conv_w   = (const float*)d_in[3];
    const float* conv_b   = (const float*)d_in[4];
    const float* asc      = (const float*)d_in[5];
    float* out = (float*)d_out;

    upsample_kernel<<<(Bq * HW + 255) / 256, 256>>>(fea);

    dim3 cg(Ww / 32, Hh / 8, Bq);
    conv_kernel<<<cg, 256>>>(guidance, conv_w, conv_b);

    sample_kernel<<<(Bq * Pn + 255) / 256, 256>>>();

    final_kernel<<<(Bq * HW + 255) / 256, 256>>>(gt, asc, out);
}